// round 2
// baseline (speedup 1.0000x reference)
#include <cuda_runtime.h>
#include <math.h>

// Problem dims
#define Bq 64
#define Hd 1024
#define Sd 128
#define Vd 32000

// ---------------------------------------------------------------------------
// Scratch: one big __device__ array (no allocations allowed). Offsets in floats.
// ---------------------------------------------------------------------------
#define OFF_X     0                         // [64*1024]   embedded inputs
#define OFF_GI    (OFF_X   + Bq*Hd)         // [64*3072]
#define OFF_GH    (OFF_GI  + Bq*3*Hd)       // [64*3072]
#define OFF_HNEW  (OFF_GH  + Bq*3*Hd)       // [64*1024]
#define OFF_AWT   (OFF_HNEW+ Bq*Hd)         // [1024*1024] attn_W transposed
#define OFF_Q     (OFF_AWT + Hd*Hd)         // [64*1024]
#define OFF_E     (OFF_Q   + Bq*Hd)         // [64*128]
#define OFF_W     (OFF_E   + Bq*Sd)         // [64*128]
#define OFF_CTX   (OFF_W   + Bq*Sd)         // [64*1024]
#define OFF_CIN   (OFF_CTX + Bq*Hd)         // [64*2048]
#define OFF_CC    (OFF_CIN + Bq*2*Hd)       // [64*1024]
#define SCRATCH_TOTAL (OFF_CC + Bq*Hd)

__device__ __align__(16) float g_scratch[SCRATCH_TOTAL];

// ---------------------------------------------------------------------------
// f32x2 packed-FMA helpers (sm_100a+): 2 MACs per instruction.
// ---------------------------------------------------------------------------
__device__ __forceinline__ unsigned long long pack2(float x, float y) {
    unsigned long long r;
    asm("mov.b64 %0, {%1, %2};" : "=l"(r) : "f"(x), "f"(y));
    return r;
}
__device__ __forceinline__ void fma2(unsigned long long& d,
                                     unsigned long long a,
                                     unsigned long long b) {
    asm("fma.rn.f32x2 %0, %1, %2, %0;" : "+l"(d) : "l"(a), "l"(b));
}
__device__ __forceinline__ void unpack2(unsigned long long v, float& lo, float& hi) {
    asm("mov.b64 {%0, %1}, %2;" : "=f"(lo), "=f"(hi) : "l"(v));
}

// ---------------------------------------------------------------------------
// Generic skinny GEMM:  C[b, j] = act( sum_k A[b,k] * W[j,k] + bias[j] )
//   b in [0,64), j tiled 64 per block, K multiple of 32.
// blockDim = 128. Each thread: 4 b x 8 j (as 4 f32x2 pairs) = 32 MACs / k-step.
// ACT: 0 = identity, 1 = tanh
// ---------------------------------------------------------------------------
template<int ACT>
__global__ void __launch_bounds__(128)
gemm_bt_kernel(const float* __restrict__ A, const float* __restrict__ W,
               const float* __restrict__ bias, float* __restrict__ C,
               int K, int ldc)
{
    const int j0 = blockIdx.x * 64;
    __shared__ float As[32][64];   // [k][b]
    __shared__ float Ws[32][64];   // [k][j]

    const int t  = threadIdx.x;
    const int lb = t & 63;             // row this thread loads (b or j-local)
    const int lk = (t >> 6) * 16;      // k sub-range: 0 or 16

    const int tx = t & 15;             // 16 threads across b
    const int ty = t >> 4;             // 8 threads across j
    const int b0 = tx * 4;
    const int jb = ty * 8;

    unsigned long long acc[4][4];
#pragma unroll
    for (int i = 0; i < 4; i++)
#pragma unroll
        for (int p = 0; p < 4; p++) acc[i][p] = 0ull;

    const float* Arow = A + (size_t)lb * K;
    const float* Wrow = W + (size_t)(j0 + lb) * K;

    for (int k0 = 0; k0 < K; k0 += 32) {
        // stage tiles (transposed to [k][row]); stores are conflict-free
#pragma unroll
        for (int i = 0; i < 4; i++) {
            float4 va = *(const float4*)(Arow + k0 + lk + i * 4);
            As[lk + i*4 + 0][lb] = va.x;
            As[lk + i*4 + 1][lb] = va.y;
            As[lk + i*4 + 2][lb] = va.z;
            As[lk + i*4 + 3][lb] = va.w;
            float4 vw = *(const float4*)(Wrow + k0 + lk + i * 4);
            Ws[lk + i*4 + 0][lb] = vw.x;
            Ws[lk + i*4 + 1][lb] = vw.y;
            Ws[lk + i*4 + 2][lb] = vw.z;
            Ws[lk + i*4 + 3][lb] = vw.w;
        }
        __syncthreads();

#pragma unroll
        for (int kk = 0; kk < 32; kk++) {
            float4 a = *(const float4*)&As[kk][b0];
            ulonglong2 w01 = *(const ulonglong2*)&Ws[kk][jb];      // (j0,j1),(j2,j3)
            ulonglong2 w23 = *(const ulonglong2*)&Ws[kk][jb + 4];  // (j4,j5),(j6,j7)
            unsigned long long ap0 = pack2(a.x, a.x);
            unsigned long long ap1 = pack2(a.y, a.y);
            unsigned long long ap2 = pack2(a.z, a.z);
            unsigned long long ap3 = pack2(a.w, a.w);
            fma2(acc[0][0], ap0, w01.x); fma2(acc[0][1], ap0, w01.y);
            fma2(acc[0][2], ap0, w23.x); fma2(acc[0][3], ap0, w23.y);
            fma2(acc[1][0], ap1, w01.x); fma2(acc[1][1], ap1, w01.y);
            fma2(acc[1][2], ap1, w23.x); fma2(acc[1][3], ap1, w23.y);
            fma2(acc[2][0], ap2, w01.x); fma2(acc[2][1], ap2, w01.y);
            fma2(acc[2][2], ap2, w23.x); fma2(acc[2][3], ap2, w23.y);
            fma2(acc[3][0], ap3, w01.x); fma2(acc[3][1], ap3, w01.y);
            fma2(acc[3][2], ap3, w23.x); fma2(acc[3][3], ap3, w23.y);
        }
        __syncthreads();
    }

#pragma unroll
    for (int bi = 0; bi < 4; bi++) {
        const int gb = b0 + bi;
#pragma unroll
        for (int p = 0; p < 4; p++) {
            float c0, c1;
            unpack2(acc[bi][p], c0, c1);
            const int j = j0 + jb + p * 2;
            if (bias) { c0 += bias[j]; c1 += bias[j + 1]; }
            if (ACT == 1) { c0 = tanhf(c0); c1 = tanhf(c1); }
            C[(size_t)gb * ldc + j]     = c0;
            C[(size_t)gb * ldc + j + 1] = c1;
        }
    }
}

// ---------------------------------------------------------------------------
// Small kernels
// ---------------------------------------------------------------------------
__global__ void gather_kernel(const int* __restrict__ seq,
                              const float* __restrict__ emb,
                              float* __restrict__ x)
{
    int idx = blockIdx.x * blockDim.x + threadIdx.x;  // 64*1024
    int b = idx >> 10, h = idx & 1023;
    x[idx] = emb[(size_t)seq[b] * Hd + h];
}

__global__ void transpose_kernel(const float* __restrict__ in,
                                 float* __restrict__ out)
{
    // out[j*1024 + i] = in[i*1024 + j], 1024x1024, 32x32 tiles, (32,8) threads
    __shared__ float tile[32][33];
    int bx = blockIdx.x * 32, by = blockIdx.y * 32;
    int tx = threadIdx.x, ty = threadIdx.y;
#pragma unroll
    for (int i = 0; i < 4; i++)
        tile[ty + i * 8][tx] = in[(size_t)(by + ty + i * 8) * Hd + bx + tx];
    __syncthreads();
#pragma unroll
    for (int i = 0; i < 4; i++)
        out[(size_t)(bx + ty + i * 8) * Hd + by + tx] = tile[tx][ty + i * 8];
}

__device__ __forceinline__ float sigmoidf_(float x) {
    return 1.0f / (1.0f + expf(-x));
}

__global__ void gru_kernel(const float* __restrict__ gi,
                           const float* __restrict__ gh,
                           const float* __restrict__ h0,
                           float* __restrict__ hnew,
                           float* __restrict__ out_h)
{
    int idx = blockIdx.x * blockDim.x + threadIdx.x;  // 64*1024
    int b = idx >> 10, h = idx & 1023;
    size_t base = (size_t)b * 3 * Hd;
    float r = sigmoidf_(gi[base + h]          + gh[base + h]);
    float z = sigmoidf_(gi[base + Hd + h]     + gh[base + Hd + h]);
    float n = tanhf(gi[base + 2 * Hd + h] + r * gh[base + 2 * Hd + h]);
    float hv = h0[idx];
    float o = (1.0f - z) * n + z * hv;
    hnew[idx] = o;
    out_h[idx] = o;
}

// energies[b,s] = q[b,:] . enc[s,b,:] + h_new[b,:] . attn_b
__global__ void __launch_bounds__(128)
energies_kernel(const float* __restrict__ hnew, const float* __restrict__ q,
                const float* __restrict__ attn_b, const float* __restrict__ enc,
                float* __restrict__ E)
{
    const int b = blockIdx.x;
    const int t = threadIdx.x;
    __shared__ float qs[Hd];
    __shared__ float red[128];

    for (int i = t; i < Hd; i += 128) qs[i] = q[(size_t)b * Hd + i];

    float p = 0.f;
    for (int i = t; i < Hd; i += 128) p += hnew[(size_t)b * Hd + i] * attn_b[i];
    red[t] = p;
    __syncthreads();
    for (int str = 64; str > 0; str >>= 1) {
        if (t < str) red[t] += red[t + str];
        __syncthreads();
    }
    const float hb = red[0];
    __syncthreads();

    const int wid = t >> 5, lane = t & 31;
    const float4* qp = (const float4*)qs;
    for (int s = wid; s < Sd; s += 4) {
        const float4* ep = (const float4*)(enc + ((size_t)s * Bq + b) * Hd);
        float acc = 0.f;
#pragma unroll
        for (int ii = 0; ii < 8; ii++) {
            int i = ii * 32 + lane;
            float4 e4 = ep[i];
            float4 q4 = qp[i];
            acc += e4.x * q4.x + e4.y * q4.y + e4.z * q4.z + e4.w * q4.w;
        }
#pragma unroll
        for (int off = 16; off > 0; off >>= 1)
            acc += __shfl_xor_sync(0xFFFFFFFFu, acc, off);
        if (lane == 0) E[b * Sd + s] = acc + hb;
    }
}

__global__ void __launch_bounds__(128)
softmax_kernel(const float* __restrict__ E, float* __restrict__ w,
               float* __restrict__ out_attn)
{
    const int b = blockIdx.x;
    const int t = threadIdx.x;   // one thread per s (S=128)
    __shared__ float red[128];
    float v = E[b * Sd + t];
    red[t] = v;
    __syncthreads();
    for (int str = 64; str > 0; str >>= 1) {
        if (t < str) red[t] = fmaxf(red[t], red[t + str]);
        __syncthreads();
    }
    float m = red[0];
    __syncthreads();
    float e = expf(v - m);
    red[t] = e;
    __syncthreads();
    for (int str = 64; str > 0; str >>= 1) {
        if (t < str) red[t] += red[t + str];
        __syncthreads();
    }
    float ww = e / red[0];
    w[b * Sd + t] = ww;
    out_attn[b * Sd + t] = ww;   // [B,1,S] layout == b*S+s
}

// ctx[b,h] = sum_s w[b,s] * enc[s,b,h]
__global__ void __launch_bounds__(256)
context_kernel(const float* __restrict__ w, const float* __restrict__ enc,
               float* __restrict__ ctx)
{
    const int b = blockIdx.x;
    const int h = blockIdx.y * 256 + threadIdx.x;
    __shared__ float ws[Sd];
    if (threadIdx.x < Sd) ws[threadIdx.x] = w[b * Sd + threadIdx.x];
    __syncthreads();
    float acc = 0.f;
#pragma unroll 8
    for (int s = 0; s < Sd; s++)
        acc += ws[s] * enc[((size_t)s * Bq + b) * Hd + h];
    ctx[(size_t)b * Hd + h] = acc;
}

__global__ void pack_kernel(const float* __restrict__ hnew,
                            const float* __restrict__ ctx,
                            float* __restrict__ cin)
{
    int idx = blockIdx.x * blockDim.x + threadIdx.x;  // 64*2048
    int b = idx >> 11, j = idx & 2047;
    cin[idx] = (j < Hd) ? hnew[(size_t)b * Hd + j]
                        : ctx[(size_t)b * Hd + (j - Hd)];
}

// ---------------------------------------------------------------------------
// Launch
// ---------------------------------------------------------------------------
extern "C" void kernel_launch(void* const* d_in, const int* in_sizes, int n_in,
                              void* d_out, int out_size)
{
    const int*   seq      = (const int*)  d_in[0];
    const float* last_h   = (const float*)d_in[1];   // [1,B,H]
    const float* enc      = (const float*)d_in[2];   // [S,B,H]
    const float* emb      = (const float*)d_in[3];   // [V,H]
    const float* W_ih     = (const float*)d_in[4];   // [3H,H]
    const float* W_hh     = (const float*)d_in[5];
    const float* b_ih     = (const float*)d_in[6];
    const float* b_hh     = (const float*)d_in[7];
    const float* attn_W   = (const float*)d_in[8];   // [H,H]
    const float* attn_b   = (const float*)d_in[9];
    const float* concat_W = (const float*)d_in[10];  // [H,2H]
    const float* concat_b = (const float*)d_in[11];
    const float* out_W    = (const float*)d_in[12];  // [V,H]
    const float* out_b    = (const float*)d_in[13];

    float* out = (float*)d_out;
    float* out_logits = out;                    // [B,V]
    float* out_h      = out + (size_t)Bq * Vd;  // [1,B,H]
    float* out_attn   = out_h + (size_t)Bq * Hd;// [B,1,S]

    void* sp = nullptr;
    cudaGetSymbolAddress(&sp, g_scratch);
    float* S = (float*)sp;
    float* g_x    = S + OFF_X;
    float* g_gi   = S + OFF_GI;
    float* g_gh   = S + OFF_GH;
    float* g_hnew = S + OFF_HNEW;
    float* g_awt  = S + OFF_AWT;
    float* g_q    = S + OFF_Q;
    float* g_E    = S + OFF_E;
    float* g_w    = S + OFF_W;
    float* g_ctx  = S + OFF_CTX;
    float* g_cin  = S + OFF_CIN;
    float* g_cc   = S + OFF_CC;

    // 1) embedding gather
    gather_kernel<<<(Bq * Hd) / 256, 256>>>(seq, emb, g_x);
    // attn_W transpose (independent; needed at step 5)
    transpose_kernel<<<dim3(Hd / 32, Hd / 32), dim3(32, 8)>>>(attn_W, g_awt);

    // 2) gi = x @ W_ih^T + b_ih ; gh = h @ W_hh^T + b_hh
    gemm_bt_kernel<0><<<3 * Hd / 64, 128>>>(g_x, W_ih, b_ih, g_gi, Hd, 3 * Hd);
    gemm_bt_kernel<0><<<3 * Hd / 64, 128>>>(last_h, W_hh, b_hh, g_gh, Hd, 3 * Hd);

    // 3) GRU combine -> h_new (also writes output region 2)
    gru_kernel<<<(Bq * Hd) / 256, 256>>>(g_gi, g_gh, last_h, g_hnew, out_h);

    // 4) q = h_new @ attn_W  (via transposed attn_W)
    gemm_bt_kernel<0><<<Hd / 64, 128>>>(g_hnew, g_awt, nullptr, g_q, Hd, Hd);

    // 5) energies + softmax + context
    energies_kernel<<<Bq, 128>>>(g_hnew, g_q, attn_b, enc, g_E);
    softmax_kernel<<<Bq, 128>>>(g_E, g_w, out_attn);
    context_kernel<<<dim3(Bq, Hd / 256), 256>>>(g_w, enc, g_ctx);

    // 6) concat -> tanh GEMM
    pack_kernel<<<(Bq * 2 * Hd) / 256, 256>>>(g_hnew, g_ctx, g_cin);
    gemm_bt_kernel<1><<<Hd / 64, 128>>>(g_cin, concat_W, concat_b, g_cc,
                                        2 * Hd, Hd);

    // 7) output logits GEMM (the big one: 64 x 32000 x 1024)
    gemm_bt_kernel<0><<<Vd / 64, 128>>>(g_cc, out_W, out_b, out_logits, Hd, Vd);
}

// round 3
// speedup vs baseline: 1.4773x; 1.4773x over previous
#include <cuda_runtime.h>
#include <math.h>

#define Bq 64
#define Hd 1024
#define Sd 128
#define Vd 32000

// ---------------------------------------------------------------------------
// Scratch (float offsets)
// ---------------------------------------------------------------------------
#define OFF_X     0                          // 64*1024
#define OFF_HNEW  (OFF_X    + Bq*Hd)         // 64*1024
#define OFF_AWT   (OFF_HNEW + Bq*Hd)         // 1024*1024
#define OFF_Q     (OFF_AWT  + Hd*Hd)         // 64*1024
#define OFF_E     (OFF_Q    + Bq*Hd)         // 64*128
#define OFF_W     (OFF_E    + Bq*Sd)         // 64*128
#define OFF_CTX   (OFF_W    + Bq*Sd)         // 64*1024
#define OFF_CIN   (OFF_CTX  + Bq*Hd)         // 64*2048
#define OFF_CC    (OFF_CIN  + Bq*2*Hd)       // 64*1024
#define OFF_PGI   (OFF_CC   + Bq*Hd)         // 8*64*3072
#define OFF_PGH   (OFF_PGI  + 8*Bq*3*Hd)     // 8*64*3072
#define OFF_PQ    (OFF_PGH  + 8*Bq*3*Hd)     // 16*64*1024
#define OFF_PCC   (OFF_PQ   + 16*Bq*Hd)      // 16*64*1024
#define SCRATCH_TOTAL (OFF_PCC + 16*Bq*Hd)

__device__ __align__(16) float g_scratch[SCRATCH_TOTAL];

// ---------------------------------------------------------------------------
// f32x2 helpers
// ---------------------------------------------------------------------------
__device__ __forceinline__ unsigned long long pack2(float x, float y) {
    unsigned long long r;
    asm("mov.b64 %0, {%1, %2};" : "=l"(r) : "f"(x), "f"(y));
    return r;
}
__device__ __forceinline__ void fma2(unsigned long long& d,
                                     unsigned long long a,
                                     unsigned long long b) {
    asm("fma.rn.f32x2 %0, %1, %2, %0;" : "+l"(d) : "l"(a), "l"(b));
}
__device__ __forceinline__ void unpack2(unsigned long long v, float& lo, float& hi) {
    asm("mov.b64 {%0, %1}, %2;" : "=f"(lo), "=f"(hi) : "l"(v));
}

// ---------------------------------------------------------------------------
// GEMM: C[b, j] = sum_k A[b,k] * W[j,k]   (b in [0,64), j tiled 128/block)
// grid = (J/128, SPLITK). If SPLIT: writes partial P[split][b][J] (no bias).
// Else: writes C[b*J + j] with bias (+tanh if ACT==1).
// block = 256 threads; thread tile 4b x 8j; k chunked by 32, reg double-buffer.
// K/gridDim.y must be a multiple of 32.
// ---------------------------------------------------------------------------
template<int ACT, bool SPLIT>
__global__ void __launch_bounds__(256)
gemm128(const float* __restrict__ A, const float* __restrict__ W,
        const float* __restrict__ bias, float* __restrict__ C,
        int K, int J)
{
    __shared__ unsigned long long As2[32][64];  // (a,a)-duplicated
    __shared__ float Ws[32][128];

    const int t  = threadIdx.x;
    const int j0 = blockIdx.x * 128;
    const int kslice = K / gridDim.y;
    const int kbeg   = blockIdx.y * kslice;
    const int nchunk = kslice >> 5;

    // staging roles
    const int lb  = t & 63;   const int kqa = t >> 6;   // A: row lb, float4 slot kqa(+4i)
    const int lw  = t & 127;  const int kqw = t >> 7;   // W: row lw, float4 slots 4*kqw+i

    const float* Ap = A + (size_t)lb * K + kbeg;
    const float* Wp = W + (size_t)(j0 + lw) * K + kbeg;

    // compute roles
    const int b0 = (t & 15) * 4;
    const int jb = (t >> 4) * 8;

    unsigned long long acc[4][4];
#pragma unroll
    for (int i = 0; i < 4; i++)
#pragma unroll
        for (int p = 0; p < 4; p++) acc[i][p] = 0ull;

    float4 ra[2], rw[4];
#pragma unroll
    for (int i = 0; i < 2; i++) ra[i] = *(const float4*)(Ap + (kqa + i * 4) * 4);
#pragma unroll
    for (int i = 0; i < 4; i++) rw[i] = *(const float4*)(Wp + (kqw * 4 + i) * 4);

    for (int c = 0; c < nchunk; c++) {
        // stage registers -> smem
#pragma unroll
        for (int i = 0; i < 2; i++) {
            const int k = (kqa + i * 4) * 4;
            As2[k + 0][lb] = pack2(ra[i].x, ra[i].x);
            As2[k + 1][lb] = pack2(ra[i].y, ra[i].y);
            As2[k + 2][lb] = pack2(ra[i].z, ra[i].z);
            As2[k + 3][lb] = pack2(ra[i].w, ra[i].w);
        }
#pragma unroll
        for (int i = 0; i < 4; i++) {
            const int k = (kqw * 4 + i) * 4;
            Ws[k + 0][lw] = rw[i].x;
            Ws[k + 1][lw] = rw[i].y;
            Ws[k + 2][lw] = rw[i].z;
            Ws[k + 3][lw] = rw[i].w;
        }
        __syncthreads();

        if (c + 1 < nchunk) {
            const int off = (c + 1) * 32;
#pragma unroll
            for (int i = 0; i < 2; i++)
                ra[i] = *(const float4*)(Ap + off + (kqa + i * 4) * 4);
#pragma unroll
            for (int i = 0; i < 4; i++)
                rw[i] = *(const float4*)(Wp + off + (kqw * 4 + i) * 4);
        }

#pragma unroll
        for (int kk = 0; kk < 32; kk++) {
            ulonglong2 a01 = *(const ulonglong2*)&As2[kk][b0];
            ulonglong2 a23 = *(const ulonglong2*)&As2[kk][b0 + 2];
            ulonglong2 wA  = *(const ulonglong2*)&Ws[kk][jb];
            ulonglong2 wB  = *(const ulonglong2*)&Ws[kk][jb + 4];
            fma2(acc[0][0], a01.x, wA.x); fma2(acc[0][1], a01.x, wA.y);
            fma2(acc[0][2], a01.x, wB.x); fma2(acc[0][3], a01.x, wB.y);
            fma2(acc[1][0], a01.y, wA.x); fma2(acc[1][1], a01.y, wA.y);
            fma2(acc[1][2], a01.y, wB.x); fma2(acc[1][3], a01.y, wB.y);
            fma2(acc[2][0], a23.x, wA.x); fma2(acc[2][1], a23.x, wA.y);
            fma2(acc[2][2], a23.x, wB.x); fma2(acc[2][3], a23.x, wB.y);
            fma2(acc[3][0], a23.y, wA.x); fma2(acc[3][1], a23.y, wA.y);
            fma2(acc[3][2], a23.y, wB.x); fma2(acc[3][3], a23.y, wB.y);
        }
        __syncthreads();
    }

    if (SPLIT) {
        float* P = C + (size_t)blockIdx.y * 64 * J;
#pragma unroll
        for (int bi = 0; bi < 4; bi++) {
#pragma unroll
            for (int p = 0; p < 4; p++) {
                float c0, c1;
                unpack2(acc[bi][p], c0, c1);
                const size_t o = (size_t)(b0 + bi) * J + j0 + jb + p * 2;
                P[o]     = c0;
                P[o + 1] = c1;
            }
        }
    } else {
#pragma unroll
        for (int bi = 0; bi < 4; bi++) {
#pragma unroll
            for (int p = 0; p < 4; p++) {
                float c0, c1;
                unpack2(acc[bi][p], c0, c1);
                const int j = j0 + jb + p * 2;
                if (bias) { c0 += bias[j]; c1 += bias[j + 1]; }
                if (ACT == 1) { c0 = tanhf(c0); c1 = tanhf(c1); }
                C[(size_t)(b0 + bi) * J + j]     = c0;
                C[(size_t)(b0 + bi) * J + j + 1] = c1;
            }
        }
    }
}

// ---------------------------------------------------------------------------
// Split-K reduce: C[idx] = act(sum_p P[p][idx] + bias[j])
// ---------------------------------------------------------------------------
template<int ACT>
__global__ void reduce_kernel(const float* __restrict__ P,
                              const float* __restrict__ bias,
                              float* __restrict__ C, int splitk, int J)
{
    const int idx = blockIdx.x * blockDim.x + threadIdx.x;  // 64*J
    const int j = idx % J;
    float s = bias ? bias[j] : 0.f;
    const size_t stride = (size_t)64 * J;
    for (int p = 0; p < splitk; p++) s += P[(size_t)p * stride + idx];
    if (ACT == 1) s = tanhf(s);
    C[idx] = s;
}

// ---------------------------------------------------------------------------
// Small kernels
// ---------------------------------------------------------------------------
__global__ void gather_kernel(const int* __restrict__ seq,
                              const float* __restrict__ emb,
                              float* __restrict__ x)
{
    int idx = blockIdx.x * blockDim.x + threadIdx.x;
    int b = idx >> 10, h = idx & 1023;
    x[idx] = emb[(size_t)seq[b] * Hd + h];
}

__global__ void transpose_kernel(const float* __restrict__ in,
                                 float* __restrict__ out)
{
    __shared__ float tile[32][33];
    int bx = blockIdx.x * 32, by = blockIdx.y * 32;
    int tx = threadIdx.x, ty = threadIdx.y;
#pragma unroll
    for (int i = 0; i < 4; i++)
        tile[ty + i * 8][tx] = in[(size_t)(by + ty + i * 8) * Hd + bx + tx];
    __syncthreads();
#pragma unroll
    for (int i = 0; i < 4; i++)
        out[(size_t)(bx + ty + i * 8) * Hd + by + tx] = tile[tx][ty + i * 8];
}

__device__ __forceinline__ float sigmoidf_(float x) {
    return 1.0f / (1.0f + expf(-x));
}

// Fused split-K reduce of gi/gh partials + GRU combine
__global__ void gru_reduce_kernel(const float* __restrict__ Pgi,
                                  const float* __restrict__ Pgh,
                                  const float* __restrict__ b_ih,
                                  const float* __restrict__ b_hh,
                                  const float* __restrict__ h0,
                                  float* __restrict__ hnew,
                                  float* __restrict__ out_h)
{
    const int idx = blockIdx.x * blockDim.x + threadIdx.x;  // 64*1024
    const int b = idx >> 10, h = idx & 1023;
    float gir = b_ih[h], giz = b_ih[Hd + h], gin = b_ih[2 * Hd + h];
    float ghr = b_hh[h], ghz = b_hh[Hd + h], ghn = b_hh[2 * Hd + h];
    const size_t base = (size_t)b * 3 * Hd + h;
    const size_t stride = (size_t)64 * 3 * Hd;
#pragma unroll
    for (int p = 0; p < 8; p++) {
        const size_t o = (size_t)p * stride + base;
        gir += Pgi[o];          ghr += Pgh[o];
        giz += Pgi[o + Hd];     ghz += Pgh[o + Hd];
        gin += Pgi[o + 2 * Hd]; ghn += Pgh[o + 2 * Hd];
    }
    float r = sigmoidf_(gir + ghr);
    float z = sigmoidf_(giz + ghz);
    float n = tanhf(gin + r * ghn);
    float o = (1.0f - z) * n + z * h0[idx];
    hnew[idx] = o;
    out_h[idx] = o;
}

// energies[b,s] = q[b,:] . enc[s,b,:] + h_new[b,:] . attn_b
// grid (64, 2), block 256
__global__ void __launch_bounds__(256)
energies_kernel(const float* __restrict__ hnew, const float* __restrict__ q,
                const float* __restrict__ attn_b, const float* __restrict__ enc,
                float* __restrict__ E)
{
    const int b = blockIdx.x;
    const int s0 = blockIdx.y * 64;
    const int t = threadIdx.x;
    __shared__ float qs[Hd];
    __shared__ float red[256];

    for (int i = t; i < Hd; i += 256) qs[i] = q[(size_t)b * Hd + i];

    float p = 0.f;
    for (int i = t; i < Hd; i += 256) p += hnew[(size_t)b * Hd + i] * attn_b[i];
    red[t] = p;
    __syncthreads();
    for (int str = 128; str > 0; str >>= 1) {
        if (t < str) red[t] += red[t + str];
        __syncthreads();
    }
    const float hb = red[0];
    __syncthreads();

    const int wid = t >> 5, lane = t & 31;
    const float4* qp = (const float4*)qs;
    for (int s = s0 + wid; s < s0 + 64; s += 8) {
        const float4* ep = (const float4*)(enc + ((size_t)s * Bq + b) * Hd);
        float acc = 0.f;
#pragma unroll
        for (int ii = 0; ii < 8; ii++) {
            int i = ii * 32 + lane;
            float4 e4 = ep[i];
            float4 q4 = qp[i];
            acc += e4.x * q4.x + e4.y * q4.y + e4.z * q4.z + e4.w * q4.w;
        }
#pragma unroll
        for (int off = 16; off > 0; off >>= 1)
            acc += __shfl_xor_sync(0xFFFFFFFFu, acc, off);
        if (lane == 0) E[b * Sd + s] = acc + hb;
    }
}

__global__ void __launch_bounds__(128)
softmax_kernel(const float* __restrict__ E, float* __restrict__ w,
               float* __restrict__ out_attn)
{
    const int b = blockIdx.x;
    const int t = threadIdx.x;
    __shared__ float red[128];
    float v = E[b * Sd + t];
    red[t] = v;
    __syncthreads();
    for (int str = 64; str > 0; str >>= 1) {
        if (t < str) red[t] = fmaxf(red[t], red[t + str]);
        __syncthreads();
    }
    float m = red[0];
    __syncthreads();
    float e = expf(v - m);
    red[t] = e;
    __syncthreads();
    for (int str = 64; str > 0; str >>= 1) {
        if (t < str) red[t] += red[t + str];
        __syncthreads();
    }
    float ww = e / red[0];
    w[b * Sd + t] = ww;
    out_attn[b * Sd + t] = ww;
}

__global__ void __launch_bounds__(256)
context_kernel(const float* __restrict__ w, const float* __restrict__ enc,
               float* __restrict__ ctx)
{
    const int b = blockIdx.x;
    const int h = blockIdx.y * 256 + threadIdx.x;
    __shared__ float ws[Sd];
    if (threadIdx.x < Sd) ws[threadIdx.x] = w[b * Sd + threadIdx.x];
    __syncthreads();
    float acc = 0.f;
#pragma unroll 8
    for (int s = 0; s < Sd; s++)
        acc += ws[s] * enc[((size_t)s * Bq + b) * Hd + h];
    ctx[(size_t)b * Hd + h] = acc;
}

__global__ void pack_kernel(const float* __restrict__ hnew,
                            const float* __restrict__ ctx,
                            float* __restrict__ cin)
{
    int idx = blockIdx.x * blockDim.x + threadIdx.x;
    int b = idx >> 11, j = idx & 2047;
    cin[idx] = (j < Hd) ? hnew[(size_t)b * Hd + j]
                        : ctx[(size_t)b * Hd + (j - Hd)];
}

// ---------------------------------------------------------------------------
// Launch
// ---------------------------------------------------------------------------
extern "C" void kernel_launch(void* const* d_in, const int* in_sizes, int n_in,
                              void* d_out, int out_size)
{
    const int*   seq      = (const int*)  d_in[0];
    const float* last_h   = (const float*)d_in[1];
    const float* enc      = (const float*)d_in[2];
    const float* emb      = (const float*)d_in[3];
    const float* W_ih     = (const float*)d_in[4];
    const float* W_hh     = (const float*)d_in[5];
    const float* b_ih     = (const float*)d_in[6];
    const float* b_hh     = (const float*)d_in[7];
    const float* attn_W   = (const float*)d_in[8];
    const float* attn_b   = (const float*)d_in[9];
    const float* concat_W = (const float*)d_in[10];
    const float* concat_b = (const float*)d_in[11];
    const float* out_W    = (const float*)d_in[12];
    const float* out_b    = (const float*)d_in[13];

    float* out = (float*)d_out;
    float* out_logits = out;
    float* out_h      = out + (size_t)Bq * Vd;
    float* out_attn   = out_h + (size_t)Bq * Hd;

    void* sp = nullptr;
    cudaGetSymbolAddress(&sp, g_scratch);
    float* S = (float*)sp;
    float* g_x    = S + OFF_X;
    float* g_hnew = S + OFF_HNEW;
    float* g_awt  = S + OFF_AWT;
    float* g_q    = S + OFF_Q;
    float* g_E    = S + OFF_E;
    float* g_w    = S + OFF_W;
    float* g_ctx  = S + OFF_CTX;
    float* g_cin  = S + OFF_CIN;
    float* g_cc   = S + OFF_CC;
    float* g_pgi  = S + OFF_PGI;
    float* g_pgh  = S + OFF_PGH;
    float* g_pq   = S + OFF_PQ;
    float* g_pcc  = S + OFF_PCC;

    // 1) embedding gather + attn_W transpose (independent)
    gather_kernel<<<(Bq * Hd) / 256, 256>>>(seq, emb, g_x);
    transpose_kernel<<<dim3(Hd / 32, Hd / 32), dim3(32, 8)>>>(attn_W, g_awt);

    // 2) gi / gh split-K GEMMs (J=3072, K=1024, splitK=8 -> kslice 128)
    gemm128<0, true><<<dim3(3 * Hd / 128, 8), 256>>>(g_x,    W_ih, nullptr, g_pgi, Hd, 3 * Hd);
    gemm128<0, true><<<dim3(3 * Hd / 128, 8), 256>>>(last_h, W_hh, nullptr, g_pgh, Hd, 3 * Hd);

    // 3) fused reduce + GRU
    gru_reduce_kernel<<<(Bq * Hd) / 256, 256>>>(g_pgi, g_pgh, b_ih, b_hh,
                                                last_h, g_hnew, out_h);

    // 4) q = h_new @ attn_W  (J=1024, K=1024, splitK=16 -> kslice 64)
    gemm128<0, true><<<dim3(Hd / 128, 16), 256>>>(g_hnew, g_awt, nullptr, g_pq, Hd, Hd);
    reduce_kernel<0><<<(Bq * Hd) / 256, 256>>>(g_pq, nullptr, g_q, 16, Hd);

    // 5) energies + softmax + context
    energies_kernel<<<dim3(Bq, 2), 256>>>(g_hnew, g_q, attn_b, enc, g_E);
    softmax_kernel<<<Bq, 128>>>(g_E, g_w, out_attn);
    context_kernel<<<dim3(Bq, Hd / 256), 256>>>(g_w, enc, g_ctx);

    // 6) concat + tanh GEMM (J=1024, K=2048, splitK=16 -> kslice 128)
    pack_kernel<<<(Bq * 2 * Hd) / 256, 256>>>(g_hnew, g_ctx, g_cin);
    gemm128<0, true><<<dim3(Hd / 128, 16), 256>>>(g_cin, concat_W, nullptr, g_pcc,
                                                  2 * Hd, Hd);
    reduce_kernel<1><<<(Bq * Hd) / 256, 256>>>(g_pcc, concat_b, g_cc, 16, Hd);

    // 7) output logits GEMM: 64 x 32000 x 1024, grid 250
    gemm128<0, false><<<dim3(Vd / 128, 1), 256>>>(g_cc, out_W, out_b,
                                                  out_logits, Hd, Vd);
}